// round 1
// baseline (speedup 1.0000x reference)
#include <cuda_runtime.h>

#define NN 100000
#define NE 600000
#define HD 128
#define LAYERS 4
#define EPSV 1e-5f

// ---------------- scratch (device globals; no allocation allowed) ----------
__device__ __align__(16) float g_h[NN * HD];   // node features
__device__ __align__(16) float g_m[NN * HD];   // message buffer / mlp temp
__device__ float g_dinv[NN];
__device__ int   g_cnt[NN];
__device__ int   g_rowstart[NN + 1];
__device__ int   g_wpos[NN];
__device__ int   g_csr_src[NE];
__device__ float g_csr_w[NE];
__device__ float g_bnsum[LAYERS * HD];
__device__ float g_bnsq[LAYERS * HD];

// ---------------- small helpers --------------------------------------------
__device__ __forceinline__ float4 f4add(float4 a, float4 b) {
    return make_float4(a.x + b.x, a.y + b.y, a.z + b.z, a.w + b.w);
}

// ---------------- setup kernels --------------------------------------------
__global__ void k_zero() {
    int i = blockIdx.x * blockDim.x + threadIdx.x;
    if (i < NN) g_cnt[i] = 0;
    if (i < LAYERS * HD) { g_bnsum[i] = 0.f; g_bnsq[i] = 0.f; }
}

__global__ void k_count(const int* __restrict__ ei) {
    int e = blockIdx.x * blockDim.x + threadIdx.x;
    if (e < NE) atomicAdd(&g_cnt[ei[NE + e]], 1);
}

// single-block exclusive scan over g_cnt + dinv
__global__ void k_scan() {
    __shared__ int ssum[1024];
    int t = threadIdx.x;
    const int CH = (NN + 1023) / 1024;   // 98
    int lo = t * CH;
    int hi = lo + CH; if (hi > NN) hi = NN;
    if (lo > NN) lo = NN;
    int s = 0;
    for (int i = lo; i < hi; i++) {
        s += g_cnt[i];
        g_dinv[i] = rsqrtf((float)g_cnt[i] + 1.0f);   // self-loop included
    }
    ssum[t] = s;
    __syncthreads();
    // Hillis-Steele inclusive scan
    for (int off = 1; off < 1024; off <<= 1) {
        int v = (t >= off) ? ssum[t - off] : 0;
        __syncthreads();
        ssum[t] += v;
        __syncthreads();
    }
    int run = ssum[t] - s;  // exclusive prefix
    for (int i = lo; i < hi; i++) {
        g_rowstart[i] = run;
        g_wpos[i] = run;
        run += g_cnt[i];
    }
    if (t == 0) g_rowstart[NN] = NE;
}

__global__ void k_fill(const int* __restrict__ ei) {
    int e = blockIdx.x * blockDim.x + threadIdx.x;
    if (e < NE) {
        int src = ei[e];
        int dst = ei[NE + e];
        int p = atomicAdd(&g_wpos[dst], 1);
        g_csr_src[p] = src;
        g_csr_w[p] = g_dinv[src] * g_dinv[dst];
    }
}

// ---------------- input projection -----------------------------------------
__global__ void k_proj(const float* __restrict__ x, const float* __restrict__ Wi,
                       const float* __restrict__ bi) {
    int i = blockIdx.x * blockDim.x + threadIdx.x;
    if (i >= NN * HD) return;
    int n = i >> 7, c = i & 127;
    const float* xr = x + n * 3;
    g_h[i] = bi[c] + xr[0] * Wi[c] + xr[1] * Wi[HD + c] + xr[2] * Wi[2 * HD + c];
}

// ---------------- GEMM: C[nrows x NC] = A[nrows x 128] * W[128 x NC] --------
// W resident in smem; 64-row tiles of A staged in smem; 8(or 4)x4 reg tiling.
template <int NC, bool BIAS_RELU>
__global__ void k_gemm(const float* __restrict__ A, const float* __restrict__ W,
                       const float* __restrict__ bias, float* __restrict__ C, int nrows) {
    constexpr int K = 128, BM = 64;
    constexpr int CG = NC / 4;        // column groups (float4 per thread)
    constexpr int RG = 256 / CG;      // row groups
    constexpr int RPT = BM / RG;      // rows per thread
    extern __shared__ float sm[];
    float* Ws = sm;                   // K * NC
    float* As = sm + K * NC;          // BM * K
    int tid = threadIdx.x;

    for (int i = tid; i < K * NC / 4; i += 256)
        ((float4*)Ws)[i] = ((const float4*)W)[i];

    int row0 = blockIdx.x * BM;
    for (int i = tid; i < BM * K / 4; i += 256) {
        int r = i / (K / 4), c4 = i % (K / 4);
        int gr = row0 + r;
        float4 v = make_float4(0, 0, 0, 0);
        if (gr < nrows) v = ((const float4*)A)[gr * (K / 4) + c4];
        ((float4*)As)[r * (K / 4) + c4] = v;
    }
    __syncthreads();

    int ct = tid % CG, rt = tid / CG;
    float acc[RPT][4];
#pragma unroll
    for (int i = 0; i < RPT; i++)
#pragma unroll
        for (int j = 0; j < 4; j++) acc[i][j] = 0.f;

#pragma unroll 4
    for (int k = 0; k < K; k++) {
        float4 w = ((const float4*)Ws)[k * CG + ct];
#pragma unroll
        for (int i = 0; i < RPT; i++) {
            float a = As[(rt * RPT + i) * K + k];
            acc[i][0] += a * w.x;
            acc[i][1] += a * w.y;
            acc[i][2] += a * w.z;
            acc[i][3] += a * w.w;
        }
    }

    float4 bv = make_float4(0, 0, 0, 0);
    if (BIAS_RELU) bv = ((const float4*)bias)[ct];
#pragma unroll
    for (int i = 0; i < RPT; i++) {
        int gr = row0 + rt * RPT + i;
        if (gr < nrows) {
            float4 v = make_float4(acc[i][0], acc[i][1], acc[i][2], acc[i][3]);
            if (BIAS_RELU) {
                v.x = fmaxf(v.x + bv.x, 0.f);
                v.y = fmaxf(v.y + bv.y, 0.f);
                v.z = fmaxf(v.z + bv.z, 0.f);
                v.w = fmaxf(v.w + bv.w, 0.f);
            }
            ((float4*)C)[gr * (NC / 4) + ct] = v;
        }
    }
}

// ---------------- aggregation + residual + bias + BN stats ------------------
// warp per node (grid-stride); lane owns channels 4l..4l+3
__global__ void k_agg(const float* __restrict__ bias, float* __restrict__ bnsum,
                      float* __restrict__ bnsq) {
    int lane = threadIdx.x & 31;
    int w = (blockIdx.x * blockDim.x + threadIdx.x) >> 5;
    int nw = (gridDim.x * blockDim.x) >> 5;
    const float4* m4 = (const float4*)g_m;
    float4* h4 = (float4*)g_h;
    float4 b = ((const float4*)bias)[lane];

    float4 lsum = make_float4(0, 0, 0, 0);
    float4 lsq = make_float4(0, 0, 0, 0);

    for (int n = w; n < NN; n += nw) {
        float di = g_dinv[n];
        float sw = di * di;                       // self-loop norm
        float4 mm = m4[n * 32 + lane];
        float4 acc = make_float4(mm.x * sw, mm.y * sw, mm.z * sw, mm.w * sw);
        int p0 = g_rowstart[n], p1 = g_rowstart[n + 1];
        for (int p = p0; p < p1; p++) {
            int s = g_csr_src[p];
            float wg = g_csr_w[p];
            float4 v = m4[s * 32 + lane];
            acc.x += v.x * wg; acc.y += v.y * wg;
            acc.z += v.z * wg; acc.w += v.w * wg;
        }
        float4 hv = h4[n * 32 + lane];
        hv.x += acc.x + b.x; hv.y += acc.y + b.y;
        hv.z += acc.z + b.z; hv.w += acc.w + b.w;
        h4[n * 32 + lane] = hv;
        lsum = f4add(lsum, hv);
        lsq.x += hv.x * hv.x; lsq.y += hv.y * hv.y;
        lsq.z += hv.z * hv.z; lsq.w += hv.w * hv.w;
    }

    // block-level reduction of BN stats, then global atomics
    __shared__ float s_sum[HD], s_sq[HD];
    for (int i = threadIdx.x; i < HD; i += blockDim.x) { s_sum[i] = 0.f; s_sq[i] = 0.f; }
    __syncthreads();
    int c = lane * 4;
    atomicAdd(&s_sum[c + 0], lsum.x); atomicAdd(&s_sum[c + 1], lsum.y);
    atomicAdd(&s_sum[c + 2], lsum.z); atomicAdd(&s_sum[c + 3], lsum.w);
    atomicAdd(&s_sq[c + 0], lsq.x);  atomicAdd(&s_sq[c + 1], lsq.y);
    atomicAdd(&s_sq[c + 2], lsq.z);  atomicAdd(&s_sq[c + 3], lsq.w);
    __syncthreads();
    for (int i = threadIdx.x; i < HD; i += blockDim.x) {
        atomicAdd(&bnsum[i], s_sum[i]);
        atomicAdd(&bnsq[i], s_sq[i]);
    }
}

// ---------------- batchnorm apply + relu ------------------------------------
__global__ void k_bn(const float* __restrict__ bng, const float* __restrict__ bnb,
                     const float* __restrict__ bnsum, const float* __restrict__ bnsq) {
    int i = blockIdx.x * blockDim.x + threadIdx.x;
    if (i >= NN * HD) return;
    int c = i & 127;
    const float invn = 1.0f / (float)NN;
    float mu = bnsum[c] * invn;
    float var = bnsq[c] * invn - mu * mu;
    float sc = bng[c] * rsqrtf(var + EPSV);
    float v = (g_h[i] - mu) * sc + bnb[c];
    g_h[i] = fmaxf(v, 0.f);
}

// ---------------- final 64 -> 8 projection ----------------------------------
__global__ void k_w3(const float* __restrict__ h2, const float* __restrict__ W3,
                     const float* __restrict__ b3, float* __restrict__ out) {
    int i = blockIdx.x * blockDim.x + threadIdx.x;
    if (i >= NN * 8) return;
    int n = i >> 3, o = i & 7;
    const float* hr = h2 + n * 64;
    float s = b3[o];
#pragma unroll 8
    for (int k = 0; k < 64; k++) s += hr[k] * W3[k * 8 + o];
    out[i] = s;
}

// ---------------- host side -------------------------------------------------
extern "C" void kernel_launch(void* const* d_in, const int* in_sizes, int n_in,
                              void* d_out, int out_size) {
    const float* x    = (const float*)d_in[0];
    const int*   ei   = (const int*)d_in[1];
    const float* Wi   = (const float*)d_in[2];
    const float* bi   = (const float*)d_in[3];
    const float* gcnW = (const float*)d_in[4];
    const float* gcnb = (const float*)d_in[5];
    const float* bng  = (const float*)d_in[6];
    const float* bnb  = (const float*)d_in[7];
    const float* W1   = (const float*)d_in[8];
    const float* b1   = (const float*)d_in[9];
    const float* W2   = (const float*)d_in[10];
    const float* b2   = (const float*)d_in[11];
    const float* W3   = (const float*)d_in[12];
    const float* b3   = (const float*)d_in[13];
    float* out = (float*)d_out;

    float *p_h, *p_m, *p_bnsum, *p_bnsq;
    cudaGetSymbolAddress((void**)&p_h, g_h);
    cudaGetSymbolAddress((void**)&p_m, g_m);
    cudaGetSymbolAddress((void**)&p_bnsum, g_bnsum);
    cudaGetSymbolAddress((void**)&p_bnsq, g_bnsq);

    constexpr int SM128 = (128 * 128 + 64 * 128) * 4;   // 96 KB
    constexpr int SM64  = (128 * 64 + 64 * 128) * 4;    // 64 KB
    cudaFuncSetAttribute((const void*)k_gemm<128, false>,
                         cudaFuncAttributeMaxDynamicSharedMemorySize, SM128);
    cudaFuncSetAttribute((const void*)k_gemm<128, true>,
                         cudaFuncAttributeMaxDynamicSharedMemorySize, SM128);
    cudaFuncSetAttribute((const void*)k_gemm<64, true>,
                         cudaFuncAttributeMaxDynamicSharedMemorySize, SM64);

    const int TILES = (NN + 63) / 64;   // 1563

    k_zero<<<(NN + 255) / 256, 256>>>();
    k_count<<<(NE + 255) / 256, 256>>>(ei);
    k_scan<<<1, 1024>>>();
    k_fill<<<(NE + 255) / 256, 256>>>(ei);
    k_proj<<<(NN * HD + 255) / 256, 256>>>(x, Wi, bi);

    for (int l = 0; l < LAYERS; l++) {
        k_gemm<128, false><<<TILES, 256, SM128>>>(p_h, gcnW + l * HD * HD, nullptr, p_m, NN);
        k_agg<<<1184, 256>>>(gcnb + l * HD, p_bnsum + l * HD, p_bnsq + l * HD);
        k_bn<<<(NN * HD + 255) / 256, 256>>>(bng + l * HD, bnb + l * HD,
                                             p_bnsum + l * HD, p_bnsq + l * HD);
    }

    k_gemm<128, true><<<TILES, 256, SM128>>>(p_h, W1, b1, p_m, NN);
    k_gemm<64, true><<<TILES, 256, SM64>>>(p_m, W2, b2, p_h, NN);
    k_w3<<<(NN * 8 + 255) / 256, 256>>>(p_h, W3, b3, out);
}

// round 4
// speedup vs baseline: 1.1934x; 1.1934x over previous
#include <cuda_runtime.h>
#include <cuda_bf16.h>
#include <cstdint>

#define NN 100000
#define NE 600000
#define HD 128
#define LAYERS 4
#define EPSV 1e-5f

// ---------------- scratch (device globals) ----------------------------------
__device__ __align__(16) float g_h[NN * HD];
__device__ __align__(16) float g_m[NN * HD];
__device__ __align__(16) __nv_bfloat16 g_hh[NN * HD];   // h split hi
__device__ __align__(16) __nv_bfloat16 g_hl[NN * HD];   // h split lo
__device__ __align__(16) __nv_bfloat16 g_mh[NN * HD];   // mlp temp hi
__device__ __align__(16) __nv_bfloat16 g_ml[NN * HD];   // mlp temp lo
__device__ __align__(16) __nv_bfloat16 g_wth[5 * HD * HD]; // W^T hi (4 gcn + W1)
__device__ __align__(16) __nv_bfloat16 g_wtl[5 * HD * HD];
__device__ __align__(16) __nv_bfloat16 g_w2th[64 * HD];
__device__ __align__(16) __nv_bfloat16 g_w2tl[64 * HD];
__device__ float g_dinv[NN];
__device__ int   g_cnt[NN];
__device__ int   g_rowstart[NN + 1];
__device__ int   g_wpos[NN];
__device__ int   g_csr_src[NE];
__device__ float g_csr_w[NE];
__device__ float g_bnsum[LAYERS * HD];
__device__ float g_bnsq[LAYERS * HD];

// ---------------- warp MMA helpers ------------------------------------------
__device__ __forceinline__ uint32_t smem_u32(const void* p) {
    uint32_t a;
    asm("{ .reg .u64 t; cvta.to.shared.u64 t, %1; cvt.u32.u64 %0, t; }" : "=r"(a) : "l"(p));
    return a;
}

__device__ __forceinline__ void ldsm_x4(uint32_t* r, uint32_t addr) {
    asm volatile("ldmatrix.sync.aligned.m8n8.x4.shared.b16 {%0,%1,%2,%3}, [%4];"
                 : "=r"(r[0]), "=r"(r[1]), "=r"(r[2]), "=r"(r[3]) : "r"(addr));
}
// NON-trans x2: for B stored n-major [n][k], thread t gets row n=t/4,
// k-pair 2(t%4),2(t%4)+1 -- exactly the m16n8k16 col-B fragment.
__device__ __forceinline__ void ldsm_x2(uint32_t* r, uint32_t addr) {
    asm volatile("ldmatrix.sync.aligned.m8n8.x2.shared.b16 {%0,%1}, [%2];"
                 : "=r"(r[0]), "=r"(r[1]) : "r"(addr));
}
__device__ __forceinline__ void mma_bf16(float* c, const uint32_t* a, const uint32_t* b) {
    asm volatile("mma.sync.aligned.m16n8k16.row.col.f32.bf16.bf16.f32 "
                 "{%0,%1,%2,%3}, {%4,%5,%6,%7}, {%8,%9}, {%0,%1,%2,%3};"
                 : "+f"(c[0]), "+f"(c[1]), "+f"(c[2]), "+f"(c[3])
                 : "r"(a[0]), "r"(a[1]), "r"(a[2]), "r"(a[3]), "r"(b[0]), "r"(b[1]));
}

// ---------------- setup kernels --------------------------------------------
__global__ void k_zero() {
    int i = blockIdx.x * blockDim.x + threadIdx.x;
    if (i < NN) g_cnt[i] = 0;
    if (i < LAYERS * HD) { g_bnsum[i] = 0.f; g_bnsq[i] = 0.f; }
}

__global__ void k_count(const int* __restrict__ ei) {
    int e = blockIdx.x * blockDim.x + threadIdx.x;
    if (e < NE) atomicAdd(&g_cnt[ei[NE + e]], 1);
}

__global__ void k_scan() {
    __shared__ int ssum[1024];
    int t = threadIdx.x;
    const int CH = (NN + 1023) / 1024;
    int lo = t * CH;
    int hi = lo + CH; if (hi > NN) hi = NN;
    if (lo > NN) lo = NN;
    int s = 0;
    for (int i = lo; i < hi; i++) {
        s += g_cnt[i];
        g_dinv[i] = rsqrtf((float)g_cnt[i] + 1.0f);
    }
    ssum[t] = s;
    __syncthreads();
    for (int off = 1; off < 1024; off <<= 1) {
        int v = (t >= off) ? ssum[t - off] : 0;
        __syncthreads();
        ssum[t] += v;
        __syncthreads();
    }
    int run = ssum[t] - s;
    for (int i = lo; i < hi; i++) {
        g_rowstart[i] = run;
        g_wpos[i] = run;
        run += g_cnt[i];
    }
    if (t == 0) g_rowstart[NN] = NE;
}

__global__ void k_fill(const int* __restrict__ ei) {
    int e = blockIdx.x * blockDim.x + threadIdx.x;
    if (e < NE) {
        int src = ei[e];
        int dst = ei[NE + e];
        int p = atomicAdd(&g_wpos[dst], 1);
        g_csr_src[p] = src;
        g_csr_w[p] = g_dinv[src] * g_dinv[dst];
    }
}

// transpose + bf16-split the weights: Wt[n][k] = W[k][n]
__global__ void k_wprep(const float* __restrict__ gcnW, const float* __restrict__ W1,
                        const float* __restrict__ W2) {
    int i = blockIdx.x * blockDim.x + threadIdx.x;
    if (i < 5 * HD * HD) {
        int m = i >> 14, rem = i & 16383, n = rem >> 7, k = rem & 127;
        const float* W = (m < 4) ? (gcnW + m * HD * HD) : W1;
        float v = W[k * HD + n];
        __nv_bfloat16 hi = __float2bfloat16(v);
        g_wth[i] = hi;
        g_wtl[i] = __float2bfloat16(v - __bfloat162float(hi));
    } else if (i < 5 * HD * HD + 64 * HD) {
        int j = i - 5 * HD * HD, n = j >> 7, k = j & 127;
        float v = W2[k * 64 + n];
        __nv_bfloat16 hi = __float2bfloat16(v);
        g_w2th[j] = hi;
        g_w2tl[j] = __float2bfloat16(v - __bfloat162float(hi));
    }
}

// ---------------- input projection (+ bf16 split) ---------------------------
__global__ void k_proj(const float* __restrict__ x, const float* __restrict__ Wi,
                       const float* __restrict__ bi) {
    int i = blockIdx.x * blockDim.x + threadIdx.x;
    if (i >= NN * HD) return;
    int n = i >> 7, c = i & 127;
    const float* xr = x + n * 3;
    float v = bi[c] + xr[0] * Wi[c] + xr[1] * Wi[HD + c] + xr[2] * Wi[2 * HD + c];
    g_h[i] = v;
    __nv_bfloat16 hi = __float2bfloat16(v);
    g_hh[i] = hi;
    g_hl[i] = __float2bfloat16(v - __bfloat162float(hi));
}

// ---------------- warp-MMA GEMM ---------------------------------------------
// C[nrows x NC] = A[nrows x 128] * Wt^T  (Wt stored [NC][128] n-major).
// A, Wt given as bf16 hi/lo splits; C = Ah*Bh + Ah*Bl + Al*Bh (3 terms).
// MODE 0: write fp32 C.  MODE 1: bias+relu, write bf16 hi/lo.  MODE 2: bias+relu fp32.
template <int NC, int MODE>
__global__ __launch_bounds__(256) void k_tgemm(
    const __nv_bfloat16* __restrict__ Ahi, const __nv_bfloat16* __restrict__ Alo,
    const __nv_bfloat16* __restrict__ Bhi, const __nv_bfloat16* __restrict__ Blo,
    const float* __restrict__ bias, float* __restrict__ Cf,
    __nv_bfloat16* __restrict__ Chi, __nv_bfloat16* __restrict__ Clo, int nrows) {
    constexpr int SA = 136;                   // padded row stride (bf16 elems)
    constexpr int WCOL = NC / 32;             // warps along N
    constexpr int WROW = 8 / WCOL;            // warps along M
    constexpr int MT = 128 / (WROW * 16);     // m16 atoms per warp
    extern __shared__ __nv_bfloat16 sm[];
    __nv_bfloat16* sAh = sm;                  // 128 * SA
    __nv_bfloat16* sAl = sAh + 128 * SA;
    __nv_bfloat16* sBh = sAl + 128 * SA;      // NC * SA
    __nv_bfloat16* sBl = sBh + NC * SA;

    int tid = threadIdx.x;
    int row0 = blockIdx.x * 128;

    // load A tile (hi/lo), guarded; rows padded with zeros
    for (int i = tid; i < 128 * 16; i += 256) {
        int r = i >> 4, j = i & 15;
        int gr = row0 + r;
        uint4 vh = make_uint4(0, 0, 0, 0), vl = make_uint4(0, 0, 0, 0);
        if (gr < nrows) {
            vh = ((const uint4*)(Ahi + (size_t)gr * 128))[j];
            vl = ((const uint4*)(Alo + (size_t)gr * 128))[j];
        }
        *(uint4*)(sAh + r * SA + j * 8) = vh;
        *(uint4*)(sAl + r * SA + j * 8) = vl;
    }
    // load B (weights)
    for (int i = tid; i < NC * 16; i += 256) {
        int r = i >> 4, j = i & 15;
        *(uint4*)(sBh + r * SA + j * 8) = ((const uint4*)(Bhi + (size_t)r * 128))[j];
        *(uint4*)(sBl + r * SA + j * 8) = ((const uint4*)(Blo + (size_t)r * 128))[j];
    }
    __syncthreads();

    int wid = tid >> 5, lane = tid & 31;
    int wr = wid % WROW, wc = wid / WROW;
    int m0 = wr * MT * 16;
    int n0 = wc * 32;

    uint32_t sbase = smem_u32(sm);
    uint32_t aAh = sbase;
    uint32_t aAl = aAh + 128 * SA * 2;
    uint32_t aBh = aAl + 128 * SA * 2;
    uint32_t aBl = aBh + NC * SA * 2;

    uint32_t arow = (uint32_t)(m0 + (lane & 15));
    uint32_t aksel = (uint32_t)((lane >> 4) * 8);
    uint32_t brow = (uint32_t)(n0 + (lane & 7));
    uint32_t bksel = (uint32_t)(((lane >> 3) & 1) * 8);

    float acc[MT][4][4];
#pragma unroll
    for (int ma = 0; ma < MT; ma++)
#pragma unroll
        for (int na = 0; na < 4; na++)
#pragma unroll
            for (int j = 0; j < 4; j++) acc[ma][na][j] = 0.f;

#pragma unroll
    for (int ks = 0; ks < 8; ks++) {
        uint32_t koffA = (uint32_t)(ks * 16) + aksel;
        uint32_t koffB = (uint32_t)(ks * 16) + bksel;
        uint32_t Af[MT][4], Bf[4][2], Bf2[4][2];

        // term 1: Ah * Bh
#pragma unroll
        for (int ma = 0; ma < MT; ma++)
            ldsm_x4(Af[ma], aAh + ((arow + ma * 16) * SA + koffA) * 2);
#pragma unroll
        for (int na = 0; na < 4; na++)
            ldsm_x2(Bf[na], aBh + ((brow + na * 8) * SA + koffB) * 2);
#pragma unroll
        for (int ma = 0; ma < MT; ma++)
#pragma unroll
            for (int na = 0; na < 4; na++)
                mma_bf16(acc[ma][na], Af[ma], Bf[na]);

        // term 2: Ah * Bl (reuse Af)
#pragma unroll
        for (int na = 0; na < 4; na++)
            ldsm_x2(Bf2[na], aBl + ((brow + na * 8) * SA + koffB) * 2);
#pragma unroll
        for (int ma = 0; ma < MT; ma++)
#pragma unroll
            for (int na = 0; na < 4; na++)
                mma_bf16(acc[ma][na], Af[ma], Bf2[na]);

        // term 3: Al * Bh (reuse Bf)
#pragma unroll
        for (int ma = 0; ma < MT; ma++)
            ldsm_x4(Af[ma], aAl + ((arow + ma * 16) * SA + koffA) * 2);
#pragma unroll
        for (int ma = 0; ma < MT; ma++)
#pragma unroll
            for (int na = 0; na < 4; na++)
                mma_bf16(acc[ma][na], Af[ma], Bf[na]);
    }

    // epilogue: D frag -> global (c0,c1: row lane/4, cols 2c,2c+1; c2,c3: row+8)
    int rbase = row0 + m0 + (lane >> 2);
    int cbase = n0 + (lane & 3) * 2;
#pragma unroll
    for (int ma = 0; ma < MT; ma++) {
#pragma unroll
        for (int half = 0; half < 2; half++) {
            int gr = rbase + ma * 16 + half * 8;
            if (gr >= nrows) continue;
#pragma unroll
            for (int na = 0; na < 4; na++) {
                float v0 = acc[ma][na][half * 2 + 0];
                float v1 = acc[ma][na][half * 2 + 1];
                int c = cbase + na * 8;
                if (MODE != 0) {
                    v0 = fmaxf(v0 + bias[c], 0.f);
                    v1 = fmaxf(v1 + bias[c + 1], 0.f);
                }
                if (MODE == 1) {
                    __nv_bfloat16 h0 = __float2bfloat16(v0);
                    __nv_bfloat16 h1 = __float2bfloat16(v1);
                    *(__nv_bfloat162*)(Chi + (size_t)gr * NC + c) = __nv_bfloat162(h0, h1);
                    *(__nv_bfloat162*)(Clo + (size_t)gr * NC + c) =
                        __nv_bfloat162(__float2bfloat16(v0 - __bfloat162float(h0)),
                                       __float2bfloat16(v1 - __bfloat162float(h1)));
                } else {
                    *(float2*)(Cf + (size_t)gr * NC + c) = make_float2(v0, v1);
                }
            }
        }
    }
}

// ---------------- aggregation + residual + bias + BN stats ------------------
__global__ void k_agg(const float* __restrict__ bias, float* __restrict__ bnsum,
                      float* __restrict__ bnsq) {
    int lane = threadIdx.x & 31;
    int w = (blockIdx.x * blockDim.x + threadIdx.x) >> 5;
    int nw = (gridDim.x * blockDim.x) >> 5;
    const float4* m4 = (const float4*)g_m;
    float4* h4 = (float4*)g_h;
    float4 b = ((const float4*)bias)[lane];

    float4 lsum = make_float4(0, 0, 0, 0);
    float4 lsq = make_float4(0, 0, 0, 0);

    for (int n = w; n < NN; n += nw) {
        float di = g_dinv[n];
        float sw = di * di;
        float4 mm = m4[n * 32 + lane];
        float4 acc = make_float4(mm.x * sw, mm.y * sw, mm.z * sw, mm.w * sw);
        int p0 = g_rowstart[n], p1 = g_rowstart[n + 1];
        for (int p = p0; p < p1; p++) {
            int s = g_csr_src[p];
            float wg = g_csr_w[p];
            float4 v = m4[s * 32 + lane];
            acc.x += v.x * wg; acc.y += v.y * wg;
            acc.z += v.z * wg; acc.w += v.w * wg;
        }
        float4 hv = h4[n * 32 + lane];
        hv.x += acc.x + b.x; hv.y += acc.y + b.y;
        hv.z += acc.z + b.z; hv.w += acc.w + b.w;
        h4[n * 32 + lane] = hv;
        lsum.x += hv.x; lsum.y += hv.y; lsum.z += hv.z; lsum.w += hv.w;
        lsq.x += hv.x * hv.x; lsq.y += hv.y * hv.y;
        lsq.z += hv.z * hv.z; lsq.w += hv.w * hv.w;
    }

    __shared__ float s_sum[HD], s_sq[HD];
    for (int i = threadIdx.x; i < HD; i += blockDim.x) { s_sum[i] = 0.f; s_sq[i] = 0.f; }
    __syncthreads();
    int c = lane * 4;
    atomicAdd(&s_sum[c + 0], lsum.x); atomicAdd(&s_sum[c + 1], lsum.y);
    atomicAdd(&s_sum[c + 2], lsum.z); atomicAdd(&s_sum[c + 3], lsum.w);
    atomicAdd(&s_sq[c + 0], lsq.x);  atomicAdd(&s_sq[c + 1], lsq.y);
    atomicAdd(&s_sq[c + 2], lsq.z);  atomicAdd(&s_sq[c + 3], lsq.w);
    __syncthreads();
    for (int i = threadIdx.x; i < HD; i += blockDim.x) {
        atomicAdd(&bnsum[i], s_sum[i]);
        atomicAdd(&bnsq[i], s_sq[i]);
    }
}

// ---------------- batchnorm apply + relu (+ bf16 split) ---------------------
__global__ void k_bn(const float* __restrict__ bng, const float* __restrict__ bnb,
                     const float* __restrict__ bnsum, const float* __restrict__ bnsq) {
    int i = blockIdx.x * blockDim.x + threadIdx.x;
    if (i >= NN * HD) return;
    int c = i & 127;
    const float invn = 1.0f / (float)NN;
    float mu = bnsum[c] * invn;
    float var = bnsq[c] * invn - mu * mu;
    float sc = bng[c] * rsqrtf(var + EPSV);
    float v = fmaxf((g_h[i] - mu) * sc + bnb[c], 0.f);
    g_h[i] = v;
    __nv_bfloat16 hi = __float2bfloat16(v);
    g_hh[i] = hi;
    g_hl[i] = __float2bfloat16(v - __bfloat162float(hi));
}

// ---------------- final 64 -> 8 projection ----------------------------------
__global__ void k_w3(const float* __restrict__ h2, const float* __restrict__ W3,
                     const float* __restrict__ b3, float* __restrict__ out) {
    int i = blockIdx.x * blockDim.x + threadIdx.x;
    if (i >= NN * 8) return;
    int n = i >> 3, o = i & 7;
    const float* hr = h2 + (size_t)n * 64;
    float s = b3[o];
#pragma unroll 8
    for (int k = 0; k < 64; k++) s += hr[k] * W3[k * 8 + o];
    out[i] = s;
}

// ---------------- host side -------------------------------------------------
extern "C" void kernel_launch(void* const* d_in, const int* in_sizes, int n_in,
                              void* d_out, int out_size) {
    const float* x    = (const float*)d_in[0];
    const int*   ei   = (const int*)d_in[1];
    const float* Wi   = (const float*)d_in[2];
    const float* bi   = (const float*)d_in[3];
    const float* gcnW = (const float*)d_in[4];
    const float* gcnb = (const float*)d_in[5];
    const float* bng  = (const float*)d_in[6];
    const float* bnb  = (const float*)d_in[7];
    const float* W1   = (const float*)d_in[8];
    const float* b1   = (const float*)d_in[9];
    const float* W2   = (const float*)d_in[10];
    const float* b2   = (const float*)d_in[11];
    const float* W3   = (const float*)d_in[12];
    const float* b3   = (const float*)d_in[13];
    float* out = (float*)d_out;

    float *p_m, *p_bnsum, *p_bnsq;
    __nv_bfloat16 *p_hh, *p_hl, *p_mh, *p_ml, *p_wth, *p_wtl, *p_w2th, *p_w2tl;
    cudaGetSymbolAddress((void**)&p_m, g_m);
    cudaGetSymbolAddress((void**)&p_bnsum, g_bnsum);
    cudaGetSymbolAddress((void**)&p_bnsq, g_bnsq);
    cudaGetSymbolAddress((void**)&p_hh, g_hh);
    cudaGetSymbolAddress((void**)&p_hl, g_hl);
    cudaGetSymbolAddress((void**)&p_mh, g_mh);
    cudaGetSymbolAddress((void**)&p_ml, g_ml);
    cudaGetSymbolAddress((void**)&p_wth, g_wth);
    cudaGetSymbolAddress((void**)&p_wtl, g_wtl);
    cudaGetSymbolAddress((void**)&p_w2th, g_w2th);
    cudaGetSymbolAddress((void**)&p_w2tl, g_w2tl);

    constexpr int SA = 136;
    constexpr int SM128 = (128 * SA * 2 + 128 * SA * 2) * 2;  // 139264 B
    constexpr int SM64  = (128 * SA * 2 + 64 * SA * 2) * 2;   // 104448 B
    cudaFuncSetAttribute((const void*)k_tgemm<128, 0>,
                         cudaFuncAttributeMaxDynamicSharedMemorySize, SM128);
    cudaFuncSetAttribute((const void*)k_tgemm<128, 1>,
                         cudaFuncAttributeMaxDynamicSharedMemorySize, SM128);
    cudaFuncSetAttribute((const void*)k_tgemm<64, 2>,
                         cudaFuncAttributeMaxDynamicSharedMemorySize, SM64);

    const int TILES = (NN + 127) / 128;   // 782

    k_zero<<<(NN + 255) / 256, 256>>>();
    k_count<<<(NE + 255) / 256, 256>>>(ei);
    k_scan<<<1, 1024>>>();
    k_fill<<<(NE + 255) / 256, 256>>>(ei);
    k_wprep<<<(5 * HD * HD + 64 * HD + 255) / 256, 256>>>(gcnW, W1, W2);
    k_proj<<<(NN * HD + 255) / 256, 256>>>(x, Wi, bi);

    for (int l = 0; l < LAYERS; l++) {
        k_tgemm<128, 0><<<TILES, 256, SM128>>>(p_hh, p_hl, p_wth + l * HD * HD,
                                               p_wtl + l * HD * HD, nullptr, p_m,
                                               nullptr, nullptr, NN);
        k_agg<<<1184, 256>>>(gcnb + l * HD, p_bnsum + l * HD, p_bnsq + l * HD);
        k_bn<<<(NN * HD + 255) / 256, 256>>>(bng + l * HD, bnb + l * HD,
                                             p_bnsum + l * HD, p_bnsq + l * HD);
    }

    k_tgemm<128, 1><<<TILES, 256, SM128>>>(p_hh, p_hl, p_wth + 4 * HD * HD,
                                           p_wtl + 4 * HD * HD, b1, nullptr,
                                           p_mh, p_ml, NN);
    k_tgemm<64, 2><<<TILES, 256, SM64>>>(p_mh, p_ml, p_w2th, p_w2tl, b2, p_m,
                                         nullptr, nullptr, NN);
    k_w3<<<(NN * 8 + 255) / 256, 256>>>(p_m, W3, b3, out);
}

// round 7
// speedup vs baseline: 1.5412x; 1.2915x over previous
// R7 submit == R5 kernel, third attempt (R5/R6 benches were broker/container
// infra failures; kernel source audited and unchanged functionally).
#include <cuda_runtime.h>
#include <cuda_bf16.h>
#include <cstdint>

#define NN 100000
#define NE 600000
#define HD 128
#define LAYERS 4
#define EPSV 1e-5f

// ---------------- scratch (device globals) ----------------------------------
__device__ __align__(16) float g_h[NN * HD];            // raw (pre-BN) node feats
__device__ __align__(16) float g_m[NN * HD];            // messages / mlp temp
__device__ __align__(16) __nv_bfloat16 g_wth[5 * HD * HD]; // W^T hi (4 gcn + W1)
__device__ __align__(16) __nv_bfloat16 g_wtl[5 * HD * HD];
__device__ __align__(16) __nv_bfloat16 g_w2th[64 * HD];
__device__ __align__(16) __nv_bfloat16 g_w2tl[64 * HD];
__device__ __align__(16) float g_trA[(LAYERS + 1) * HD];  // BN affine scale
__device__ __align__(16) float g_trB[(LAYERS + 1) * HD];  // BN affine shift
__device__ float g_dinv[NN];
__device__ int   g_cnt[NN];
__device__ int   g_rowstart[NN + 1];
__device__ int   g_wpos[NN];
__device__ __align__(8) int2 g_csr[NE];                 // (src, bitcast norm)
__device__ float g_bnsum[LAYERS * HD];
__device__ float g_bnsq[LAYERS * HD];

// ---------------- warp MMA helpers ------------------------------------------
__device__ __forceinline__ uint32_t smem_u32(const void* p) {
    uint32_t a;
    asm("{ .reg .u64 t; cvta.to.shared.u64 t, %1; cvt.u32.u64 %0, t; }" : "=r"(a) : "l"(p));
    return a;
}
__device__ __forceinline__ void ldsm_x4(uint32_t* r, uint32_t addr) {
    asm volatile("ldmatrix.sync.aligned.m8n8.x4.shared.b16 {%0,%1,%2,%3}, [%4];"
                 : "=r"(r[0]), "=r"(r[1]), "=r"(r[2]), "=r"(r[3]) : "r"(addr));
}
__device__ __forceinline__ void ldsm_x2(uint32_t* r, uint32_t addr) {
    asm volatile("ldmatrix.sync.aligned.m8n8.x2.shared.b16 {%0,%1}, [%2];"
                 : "=r"(r[0]), "=r"(r[1]) : "r"(addr));
}
__device__ __forceinline__ void mma_bf16(float* c, const uint32_t* a, const uint32_t* b) {
    asm volatile("mma.sync.aligned.m16n8k16.row.col.f32.bf16.bf16.f32 "
                 "{%0,%1,%2,%3}, {%4,%5,%6,%7}, {%8,%9}, {%0,%1,%2,%3};"
                 : "+f"(c[0]), "+f"(c[1]), "+f"(c[2]), "+f"(c[3])
                 : "r"(a[0]), "r"(a[1]), "r"(a[2]), "r"(a[3]), "r"(b[0]), "r"(b[1]));
}

// ---------------- setup kernels --------------------------------------------
__global__ void k_zero() {
    int i = blockIdx.x * blockDim.x + threadIdx.x;
    if (i < NN) g_cnt[i] = 0;
    if (i < LAYERS * HD) { g_bnsum[i] = 0.f; g_bnsq[i] = 0.f; }
    if (i < HD) { g_trA[i] = 1.f; g_trB[i] = 0.f; }   // slot 0 = identity
}

__global__ void k_count(const int* __restrict__ ei) {
    int e = blockIdx.x * blockDim.x + threadIdx.x;
    if (e < NE) atomicAdd(&g_cnt[ei[NE + e]], 1);
}

__global__ void k_scan() {
    __shared__ int ssum[1024];
    int t = threadIdx.x;
    const int CH = (NN + 1023) / 1024;
    int lo = t * CH;
    int hi = lo + CH; if (hi > NN) hi = NN;
    if (lo > NN) lo = NN;
    int s = 0;
    for (int i = lo; i < hi; i++) {
        s += g_cnt[i];
        g_dinv[i] = rsqrtf((float)g_cnt[i] + 1.0f);
    }
    ssum[t] = s;
    __syncthreads();
    for (int off = 1; off < 1024; off <<= 1) {
        int v = (t >= off) ? ssum[t - off] : 0;
        __syncthreads();
        ssum[t] += v;
        __syncthreads();
    }
    int run = ssum[t] - s;
    for (int i = lo; i < hi; i++) {
        g_rowstart[i] = run;
        g_wpos[i] = run;
        run += g_cnt[i];
    }
    if (t == 0) g_rowstart[NN] = NE;
}

__global__ void k_fill(const int* __restrict__ ei) {
    int e = blockIdx.x * blockDim.x + threadIdx.x;
    if (e < NE) {
        int src = ei[e];
        int dst = ei[NE + e];
        int p = atomicAdd(&g_wpos[dst], 1);
        g_csr[p] = make_int2(src, __float_as_int(g_dinv[src] * g_dinv[dst]));
    }
}

// transpose + bf16-split the weights: Wt[n][k] = W[k][n]
__global__ void k_wprep(const float* __restrict__ gcnW, const float* __restrict__ W1,
                        const float* __restrict__ W2) {
    int i = blockIdx.x * blockDim.x + threadIdx.x;
    if (i < 5 * HD * HD) {
        int m = i >> 14, rem = i & 16383, n = rem >> 7, k = rem & 127;
        const float* W = (m < 4) ? (gcnW + m * HD * HD) : W1;
        float v = W[k * HD + n];
        __nv_bfloat16 hi = __float2bfloat16(v);
        g_wth[i] = hi;
        g_wtl[i] = __float2bfloat16(v - __bfloat162float(hi));
    } else if (i < 5 * HD * HD + 64 * HD) {
        int j = i - 5 * HD * HD, n = j >> 7, k = j & 127;
        float v = W2[k * 64 + n];
        __nv_bfloat16 hi = __float2bfloat16(v);
        g_w2th[j] = hi;
        g_w2tl[j] = __float2bfloat16(v - __bfloat162float(hi));
    }
}

// ---------------- input projection -----------------------------------------
__global__ void k_proj(const float* __restrict__ x, const float* __restrict__ Wi,
                       const float* __restrict__ bi) {
    int i = blockIdx.x * blockDim.x + threadIdx.x;
    if (i >= NN * HD) return;
    int n = i >> 7, c = i & 127;
    const float* xr = x + n * 3;
    g_h[i] = bi[c] + xr[0] * Wi[c] + xr[1] * Wi[HD + c] + xr[2] * Wi[2 * HD + c];
}

// ---------------- BN -> affine transform prep -------------------------------
__global__ void k_bnprep(const float* __restrict__ bng, const float* __restrict__ bnb,
                         const float* __restrict__ bnsum, const float* __restrict__ bnsq,
                         float* __restrict__ trA, float* __restrict__ trB) {
    int c = threadIdx.x;
    const float invn = 1.0f / (float)NN;
    float mu = bnsum[c] * invn;
    float var = bnsq[c] * invn - mu * mu;
    float A = bng[c] * rsqrtf(var + EPSV);
    trA[c] = A;
    trB[c] = bnb[c] - mu * A;
}

// ---------------- warp-MMA GEMM with fused BN/ReLU + bf16 split on load -----
// C[nrows x NC] = f(A_raw) * Wt^T, f(v) = relu?max(v*trA+trB,0):(v*trA+trB)
// per channel. Wt stored [NC][128] n-major as bf16 hi/lo.
// BM=64 rows/CTA. MODE 0: plain fp32 store. MODE 1: bias+relu fp32 store.
template <int NC, int MODE>
__global__ __launch_bounds__(256) void k_tgemm(
    const float* __restrict__ Araw, const float* __restrict__ trA,
    const float* __restrict__ trB, int relu,
    const __nv_bfloat16* __restrict__ Bhi, const __nv_bfloat16* __restrict__ Blo,
    const float* __restrict__ bias, float* __restrict__ Cf, int nrows) {
    constexpr int SA = 136;                   // padded row stride (bf16 elems)
    constexpr int BM = 64;
    constexpr int WCOL = NC / 32;             // warps along N
    constexpr int WROW = 8 / WCOL;            // warps along M
    constexpr int MT = BM / (WROW * 16);      // m16 atoms per warp
    extern __shared__ __nv_bfloat16 sm[];
    __nv_bfloat16* sAh = sm;                  // BM * SA
    __nv_bfloat16* sAl = sAh + BM * SA;
    __nv_bfloat16* sBh = sAl + BM * SA;       // NC * SA
    __nv_bfloat16* sBl = sBh + NC * SA;

    int tid = threadIdx.x;
    int row0 = blockIdx.x * BM;

    // load A tile: fp32 -> affine(+relu) -> split hi/lo -> smem
    for (int i = tid; i < BM * 32; i += 256) {
        int r = i >> 5, j = i & 31;           // j: float4 group (channels 4j..4j+3)
        int gr = row0 + r;
        float4 v = make_float4(0, 0, 0, 0);
        if (gr < nrows) v = ((const float4*)(Araw + (size_t)gr * 128))[j];
        float4 a = ((const float4*)trA)[j];
        float4 b = ((const float4*)trB)[j];
        float t0 = fmaf(v.x, a.x, b.x), t1 = fmaf(v.y, a.y, b.y);
        float t2 = fmaf(v.z, a.z, b.z), t3 = fmaf(v.w, a.w, b.w);
        if (relu) {
            t0 = fmaxf(t0, 0.f); t1 = fmaxf(t1, 0.f);
            t2 = fmaxf(t2, 0.f); t3 = fmaxf(t3, 0.f);
        }
        __nv_bfloat16 h0 = __float2bfloat16(t0), h1 = __float2bfloat16(t1);
        __nv_bfloat16 h2 = __float2bfloat16(t2), h3 = __float2bfloat16(t3);
        __nv_bfloat162 hh01(h0, h1), hh23(h2, h3);
        __nv_bfloat162 ll01(__float2bfloat16(t0 - __bfloat162float(h0)),
                            __float2bfloat16(t1 - __bfloat162float(h1)));
        __nv_bfloat162 ll23(__float2bfloat16(t2 - __bfloat162float(h2)),
                            __float2bfloat16(t3 - __bfloat162float(h3)));
        *(uint2*)(sAh + r * SA + j * 4) =
            make_uint2(*(uint32_t*)&hh01, *(uint32_t*)&hh23);
        *(uint2*)(sAl + r * SA + j * 4) =
            make_uint2(*(uint32_t*)&ll01, *(uint32_t*)&ll23);
    }
    // load B (weights, already split)
    for (int i = tid; i < NC * 16; i += 256) {
        int r = i >> 4, j = i & 15;
        *(uint4*)(sBh + r * SA + j * 8) = ((const uint4*)(Bhi + (size_t)r * 128))[j];
        *(uint4*)(sBl + r * SA + j * 8) = ((const uint4*)(Blo + (size_t)r * 128))[j];
    }
    __syncthreads();

    int wid = tid >> 5, lane = tid & 31;
    int wr = wid % WROW, wc = wid / WROW;
    int m0 = wr * MT * 16;
    int n0 = wc * 32;

    uint32_t sbase = smem_u32(sm);
    uint32_t aAh = sbase;
    uint32_t aAl = aAh + BM * SA * 2;
    uint32_t aBh = aAl + BM * SA * 2;
    uint32_t aBl = aBh + NC * SA * 2;

    uint32_t arow = (uint32_t)(m0 + (lane & 15));
    uint32_t aksel = (uint32_t)((lane >> 4) * 8);
    uint32_t brow = (uint32_t)(n0 + (lane & 7));
    uint32_t bksel = (uint32_t)(((lane >> 3) & 1) * 8);

    float acc[MT][4][4];
#pragma unroll
    for (int ma = 0; ma < MT; ma++)
#pragma unroll
        for (int na = 0; na < 4; na++)
#pragma unroll
            for (int j = 0; j < 4; j++) acc[ma][na][j] = 0.f;

#pragma unroll
    for (int ks = 0; ks < 8; ks++) {
        uint32_t koffA = (uint32_t)(ks * 16) + aksel;
        uint32_t koffB = (uint32_t)(ks * 16) + bksel;
        uint32_t Af[MT][4], Bf[4][2], Bf2[4][2];

        // term 1: Ah * Bh
#pragma unroll
        for (int ma = 0; ma < MT; ma++)
            ldsm_x4(Af[ma], aAh + ((arow + ma * 16) * SA + koffA) * 2);
#pragma unroll
        for (int na = 0; na < 4; na++)
            ldsm_x2(Bf[na], aBh + ((brow + na * 8) * SA + koffB) * 2);
#pragma unroll
        for (int ma = 0; ma < MT; ma++)
#pragma unroll
            for (int na = 0; na < 4; na++)
                mma_bf16(acc[ma][na], Af[ma], Bf[na]);

        // term 2: Ah * Bl (reuse Af)
#pragma unroll
        for (int na = 0; na < 4; na++)
            ldsm_x2(Bf2[na], aBl + ((brow + na * 8) * SA + koffB) * 2);
#pragma unroll
        for (int ma = 0; ma < MT; ma++)
#pragma unroll
            for (int na = 0; na < 4; na++)
                mma_bf16(acc[ma][na], Af[ma], Bf2[na]);

        // term 3: Al * Bh (reuse Bf)
#pragma unroll
        for (int ma = 0; ma < MT; ma++)
            ldsm_x4(Af[ma], aAl + ((arow + ma * 16) * SA + koffA) * 2);
#pragma unroll
        for (int ma = 0; ma < MT; ma++)
#pragma unroll
            for (int na = 0; na < 4; na++)
                mma_bf16(acc[ma][na], Af[ma], Bf[na]);
    }

    // epilogue
    int rbase = row0 + m0 + (lane >> 2);
    int cbase = n0 + (lane & 3) * 2;
#pragma unroll
    for (int ma = 0; ma < MT; ma++) {
#pragma unroll
        for (int half = 0; half < 2; half++) {
            int gr = rbase + ma * 16 + half * 8;
            if (gr >= nrows) continue;
#pragma unroll
            for (int na = 0; na < 4; na++) {
                float v0 = acc[ma][na][half * 2 + 0];
                float v1 = acc[ma][na][half * 2 + 1];
                int c = cbase + na * 8;
                if (MODE == 1) {
                    v0 = fmaxf(v0 + bias[c], 0.f);
                    v1 = fmaxf(v1 + bias[c + 1], 0.f);
                }
                *(float2*)(Cf + (size_t)gr * NC + c) = make_float2(v0, v1);
            }
        }
    }
}

// ---------------- aggregation + residual(BN fused) + bias + BN stats --------
__global__ void k_agg(const float* __restrict__ trA, const float* __restrict__ trB,
                      int relu, const float* __restrict__ bias,
                      float* __restrict__ bnsum, float* __restrict__ bnsq) {
    int lane = threadIdx.x & 31;
    int w = (blockIdx.x * blockDim.x + threadIdx.x) >> 5;
    int nw = (gridDim.x * blockDim.x) >> 5;
    const float4* m4 = (const float4*)g_m;
    float4* h4 = (float4*)g_h;
    float4 b = ((const float4*)bias)[lane];
    float4 tA = ((const float4*)trA)[lane];
    float4 tB = ((const float4*)trB)[lane];

    float4 lsum = make_float4(0, 0, 0, 0);
    float4 lsq = make_float4(0, 0, 0, 0);

    for (int n = w; n < NN; n += nw) {
        float di = g_dinv[n];
        float sw = di * di;
        float4 mm = m4[(size_t)n * 32 + lane];
        float4 acc = make_float4(mm.x * sw, mm.y * sw, mm.z * sw, mm.w * sw);
        int p0 = g_rowstart[n], p1 = g_rowstart[n + 1];
        int p = p0;
        for (; p + 2 <= p1; p += 2) {
            int2 e0 = g_csr[p], e1 = g_csr[p + 1];
            float4 v0 = m4[(size_t)e0.x * 32 + lane];
            float4 v1 = m4[(size_t)e1.x * 32 + lane];
            float w0 = __int_as_float(e0.y), w1 = __int_as_float(e1.y);
            acc.x += v0.x * w0 + v1.x * w1;
            acc.y += v0.y * w0 + v1.y * w1;
            acc.z += v0.z * w0 + v1.z * w1;
            acc.w += v0.w * w0 + v1.w * w1;
        }
        if (p < p1) {
            int2 e0 = g_csr[p];
            float4 v0 = m4[(size_t)e0.x * 32 + lane];
            float w0 = __int_as_float(e0.y);
            acc.x += v0.x * w0; acc.y += v0.y * w0;
            acc.z += v0.z * w0; acc.w += v0.w * w0;
        }
        // apply previous layer's BN affine (+relu) to raw h, then residual add
        float4 hv = h4[(size_t)n * 32 + lane];
        float p0f = fmaf(hv.x, tA.x, tB.x), p1f = fmaf(hv.y, tA.y, tB.y);
        float p2f = fmaf(hv.z, tA.z, tB.z), p3f = fmaf(hv.w, tA.w, tB.w);
        if (relu) {
            p0f = fmaxf(p0f, 0.f); p1f = fmaxf(p1f, 0.f);
            p2f = fmaxf(p2f, 0.f); p3f = fmaxf(p3f, 0.f);
        }
        hv.x = p0f + acc.x + b.x; hv.y = p1f + acc.y + b.y;
        hv.z = p2f + acc.z + b.z; hv.w = p3f + acc.w + b.w;
        h4[(size_t)n * 32 + lane] = hv;
        lsum.x += hv.x; lsum.y += hv.y; lsum.z += hv.z; lsum.w += hv.w;
        lsq.x += hv.x * hv.x; lsq.y += hv.y * hv.y;
        lsq.z += hv.z * hv.z; lsq.w += hv.w * hv.w;
    }

    __shared__ float s_sum[HD], s_sq[HD];
    for (int i = threadIdx.x; i < HD; i += blockDim.x) { s_sum[i] = 0.f; s_sq[i] = 0.f; }
    __syncthreads();
    int c = lane * 4;
    atomicAdd(&s_sum[c + 0], lsum.x); atomicAdd(&s_sum[c + 1], lsum.y);
    atomicAdd(&s_sum[c + 2], lsum.z); atomicAdd(&s_sum[c + 3], lsum.w);
    atomicAdd(&s_sq[c + 0], lsq.x);  atomicAdd(&s_sq[c + 1], lsq.y);
    atomicAdd(&s_sq[c + 2], lsq.z);  atomicAdd(&s_sq[c + 3], lsq.w);
    __syncthreads();
    for (int i = threadIdx.x; i < HD; i += blockDim.x) {
        atomicAdd(&bnsum[i], s_sum[i]);
        atomicAdd(&bnsq[i], s_sq[i]);
    }
}

// ---------------- final 64 -> 8 projection ----------------------------------
__global__ void k_w3(const float* __restrict__ h2, const float* __restrict__ W3,
                     const float* __restrict__ b3, float* __restrict__ out) {
    int i = blockIdx.x * blockDim.x + threadIdx.x;
    if (i >= NN * 8) return;
    int n = i >> 3, o = i & 7;
    const float* hr = h2 + (size_t)n * 64;
    float s = b3[o];
#pragma unroll 8
    for (int k = 0; k < 64; k++) s += hr[k] * W3[k * 8 + o];
    out[i] = s;
}

// ---------------- host side -------------------------------------------------
extern "C" void kernel_launch(void* const* d_in, const int* in_sizes, int n_in,
                              void* d_out, int out_size) {
    const float* x    = (const float*)d_in[0];
    const int*   ei   = (const int*)d_in[1];
    const float* Wi   = (const float*)d_in[2];
    const float* bi   = (const float*)d_in[3];
    const float* gcnW = (const float*)d_in[4];
    const float* gcnb = (const float*)d_in[5];
    const float* bng  = (const float*)d_in[6];
    const float* bnb  = (const float*)d_in[7];
    const float* W1   = (const float*)d_in[8];
    const float* b1   = (const float*)d_in[9];
    const float* W2   = (const float*)d_in[10];
    const float* b2   = (const float*)d_in[11];
    const float* W3   = (const float*)d_in[12];
    const float* b3   = (const float*)d_in[13];
    float* out = (float*)d_out;

    float *p_h, *p_m, *p_bnsum, *p_bnsq, *p_trA, *p_trB;
    __nv_bfloat16 *p_wth, *p_wtl, *p_w2th, *p_w2tl;
    cudaGetSymbolAddress((void**)&p_h, g_h);
    cudaGetSymbolAddress((void**)&p_m, g_m);
    cudaGetSymbolAddress((void**)&p_bnsum, g_bnsum);
    cudaGetSymbolAddress((void**)&p_bnsq, g_bnsq);
    cudaGetSymbolAddress((void**)&p_trA, g_trA);
    cudaGetSymbolAddress((void**)&p_trB, g_trB);
    cudaGetSymbolAddress((void**)&p_wth, g_wth);
    cudaGetSymbolAddress((void**)&p_wtl, g_wtl);
    cudaGetSymbolAddress((void**)&p_w2th, g_w2th);
    cudaGetSymbolAddress((void**)&p_w2tl, g_w2tl);

    constexpr int SA = 136;
    constexpr int SM128 = (64 * 2 + 128 * 2) * SA * 2;  // 104448 B -> 2 CTA/SM
    constexpr int SM64  = (64 * 2 + 64 * 2) * SA * 2;   // 69632 B
    cudaFuncSetAttribute((const void*)k_tgemm<128, 0>,
                         cudaFuncAttributeMaxDynamicSharedMemorySize, SM128);
    cudaFuncSetAttribute((const void*)k_tgemm<128, 1>,
                         cudaFuncAttributeMaxDynamicSharedMemorySize, SM128);
    cudaFuncSetAttribute((const void*)k_tgemm<64, 1>,
                         cudaFuncAttributeMaxDynamicSharedMemorySize, SM64);

    const int TILES = (NN + 63) / 64;   // 1563

    k_zero<<<(NN + 255) / 256, 256>>>();
    k_count<<<(NE + 255) / 256, 256>>>(ei);
    k_scan<<<1, 1024>>>();
    k_fill<<<(NE + 255) / 256, 256>>>(ei);
    k_wprep<<<(5 * HD * HD + 64 * HD + 255) / 256, 256>>>(gcnW, W1, W2);
    k_proj<<<(NN * HD + 255) / 256, 256>>>(x, Wi, bi);

    for (int l = 0; l < LAYERS; l++) {
        k_tgemm<128, 0><<<TILES, 256, SM128>>>(
            p_h, p_trA + l * HD, p_trB + l * HD, l > 0,
            p_wth + l * HD * HD, p_wtl + l * HD * HD, nullptr, p_m, NN);
        k_agg<<<1184, 256>>>(p_trA + l * HD, p_trB + l * HD, l > 0, gcnb + l * HD,
                             p_bnsum + l * HD, p_bnsq + l * HD);
        k_bnprep<<<1, 128>>>(bng + l * HD, bnb + l * HD, p_bnsum + l * HD,
                             p_bnsq + l * HD, p_trA + (l + 1) * HD,
                             p_trB + (l + 1) * HD);
    }

    k_tgemm<128, 1><<<TILES, 256, SM128>>>(
        p_h, p_trA + LAYERS * HD, p_trB + LAYERS * HD, 1,
        p_wth + 4 * HD * HD, p_wtl + 4 * HD * HD, b1, p_m, NN);
    k_tgemm<64, 1><<<TILES, 256, SM64>>>(
        p_m, p_trA, p_trB, 0, p_w2th, p_w2tl, b2, p_h, NN);
    k_w3<<<(NN * 8 + 255) / 256, 256>>>(p_h, W3, b3, out);
}

// round 8
// speedup vs baseline: 1.8081x; 1.1731x over previous
// R8: persistent GEMM (B resident in smem, grid=296) + fp16 GCN messages.
#include <cuda_runtime.h>
#include <cuda_bf16.h>
#include <cuda_fp16.h>
#include <cstdint>

#define NN 100000
#define NE 600000
#define HD 128
#define LAYERS 4
#define EPSV 1e-5f
#define GEMM_GRID 296

// ---------------- scratch (device globals) ----------------------------------
__device__ __align__(16) float g_h[NN * HD];            // raw (pre-BN) node feats
__device__ __align__(16) float g_m[NN * HD];            // fp32 mlp temp; fp16 msgs alias
__device__ __align__(16) __nv_bfloat16 g_wth[5 * HD * HD]; // W^T hi (4 gcn + W1)
__device__ __align__(16) __nv_bfloat16 g_wtl[5 * HD * HD];
__device__ __align__(16) __nv_bfloat16 g_w2th[64 * HD];
__device__ __align__(16) __nv_bfloat16 g_w2tl[64 * HD];
__device__ __align__(16) float g_trA[(LAYERS + 1) * HD];  // BN affine scale
__device__ __align__(16) float g_trB[(LAYERS + 1) * HD];  // BN affine shift
__device__ float g_dinv[NN];
__device__ int   g_cnt[NN];
__device__ int   g_rowstart[NN + 1];
__device__ int   g_wpos[NN];
__device__ __align__(8) int2 g_csr[NE];                 // (src, bitcast norm)
__device__ float g_bnsum[LAYERS * HD];
__device__ float g_bnsq[LAYERS * HD];

// ---------------- warp MMA helpers ------------------------------------------
__device__ __forceinline__ uint32_t smem_u32(const void* p) {
    uint32_t a;
    asm("{ .reg .u64 t; cvta.to.shared.u64 t, %1; cvt.u32.u64 %0, t; }" : "=r"(a) : "l"(p));
    return a;
}
__device__ __forceinline__ void ldsm_x4(uint32_t* r, uint32_t addr) {
    asm volatile("ldmatrix.sync.aligned.m8n8.x4.shared.b16 {%0,%1,%2,%3}, [%4];"
                 : "=r"(r[0]), "=r"(r[1]), "=r"(r[2]), "=r"(r[3]) : "r"(addr));
}
__device__ __forceinline__ void ldsm_x2(uint32_t* r, uint32_t addr) {
    asm volatile("ldmatrix.sync.aligned.m8n8.x2.shared.b16 {%0,%1}, [%2];"
                 : "=r"(r[0]), "=r"(r[1]) : "r"(addr));
}
__device__ __forceinline__ void mma_bf16(float* c, const uint32_t* a, const uint32_t* b) {
    asm volatile("mma.sync.aligned.m16n8k16.row.col.f32.bf16.bf16.f32 "
                 "{%0,%1,%2,%3}, {%4,%5,%6,%7}, {%8,%9}, {%0,%1,%2,%3};"
                 : "+f"(c[0]), "+f"(c[1]), "+f"(c[2]), "+f"(c[3])
                 : "r"(a[0]), "r"(a[1]), "r"(a[2]), "r"(a[3]), "r"(b[0]), "r"(b[1]));
}

// ---------------- setup kernels --------------------------------------------
__global__ void k_zero() {
    int i = blockIdx.x * blockDim.x + threadIdx.x;
    if (i < NN) g_cnt[i] = 0;
    if (i < LAYERS * HD) { g_bnsum[i] = 0.f; g_bnsq[i] = 0.f; }
    if (i < HD) { g_trA[i] = 1.f; g_trB[i] = 0.f; }   // slot 0 = identity
}

__global__ void k_count(const int* __restrict__ ei) {
    int e = blockIdx.x * blockDim.x + threadIdx.x;
    if (e < NE) atomicAdd(&g_cnt[ei[NE + e]], 1);
}

__global__ void k_scan() {
    __shared__ int ssum[1024];
    int t = threadIdx.x;
    const int CH = (NN + 1023) / 1024;
    int lo = t * CH;
    int hi = lo + CH; if (hi > NN) hi = NN;
    if (lo > NN) lo = NN;
    int s = 0;
    for (int i = lo; i < hi; i++) {
        s += g_cnt[i];
        g_dinv[i] = rsqrtf((float)g_cnt[i] + 1.0f);
    }
    ssum[t] = s;
    __syncthreads();
    for (int off = 1; off < 1024; off <<= 1) {
        int v = (t >= off) ? ssum[t - off] : 0;
        __syncthreads();
        ssum[t] += v;
        __syncthreads();
    }
    int run = ssum[t] - s;
    for (int i = lo; i < hi; i++) {
        g_rowstart[i] = run;
        g_wpos[i] = run;
        run += g_cnt[i];
    }
    if (t == 0) g_rowstart[NN] = NE;
}

__global__ void k_fill(const int* __restrict__ ei) {
    int e = blockIdx.x * blockDim.x + threadIdx.x;
    if (e < NE) {
        int src = ei[e];
        int dst = ei[NE + e];
        int p = atomicAdd(&g_wpos[dst], 1);
        g_csr[p] = make_int2(src, __float_as_int(g_dinv[src] * g_dinv[dst]));
    }
}

// transpose + bf16-split the weights: Wt[n][k] = W[k][n]
__global__ void k_wprep(const float* __restrict__ gcnW, const float* __restrict__ W1,
                        const float* __restrict__ W2) {
    int i = blockIdx.x * blockDim.x + threadIdx.x;
    if (i < 5 * HD * HD) {
        int m = i >> 14, rem = i & 16383, n = rem >> 7, k = rem & 127;
        const float* W = (m < 4) ? (gcnW + m * HD * HD) : W1;
        float v = W[k * HD + n];
        __nv_bfloat16 hi = __float2bfloat16(v);
        g_wth[i] = hi;
        g_wtl[i] = __float2bfloat16(v - __bfloat162float(hi));
    } else if (i < 5 * HD * HD + 64 * HD) {
        int j = i - 5 * HD * HD, n = j >> 7, k = j & 127;
        float v = W2[k * 64 + n];
        __nv_bfloat16 hi = __float2bfloat16(v);
        g_w2th[j] = hi;
        g_w2tl[j] = __float2bfloat16(v - __bfloat162float(hi));
    }
}

// ---------------- input projection -----------------------------------------
__global__ void k_proj(const float* __restrict__ x, const float* __restrict__ Wi,
                       const float* __restrict__ bi) {
    int i = blockIdx.x * blockDim.x + threadIdx.x;
    if (i >= NN * HD) return;
    int n = i >> 7, c = i & 127;
    const float* xr = x + n * 3;
    g_h[i] = bi[c] + xr[0] * Wi[c] + xr[1] * Wi[HD + c] + xr[2] * Wi[2 * HD + c];
}

// ---------------- BN -> affine transform prep -------------------------------
__global__ void k_bnprep(const float* __restrict__ bng, const float* __restrict__ bnb,
                         const float* __restrict__ bnsum, const float* __restrict__ bnsq,
                         float* __restrict__ trA, float* __restrict__ trB) {
    int c = threadIdx.x;
    const float invn = 1.0f / (float)NN;
    float mu = bnsum[c] * invn;
    float var = bnsq[c] * invn - mu * mu;
    float A = bng[c] * rsqrtf(var + EPSV);
    trA[c] = A;
    trB[c] = bnb[c] - mu * A;
}

// ---------------- persistent warp-MMA GEMM ----------------------------------
// C[nrows x NC] = f(A_raw) * Wt^T, f = per-channel affine (+relu).
// B (weights, bf16 hi/lo) loaded into smem ONCE; CTA loops over 64-row tiles.
// MODE 0: store fp16 (messages).  MODE 1: bias+relu, store fp32.
template <int NC, int MODE>
__global__ __launch_bounds__(256) void k_tgemm(
    const float* __restrict__ Araw, const float* __restrict__ trA,
    const float* __restrict__ trB, int relu,
    const __nv_bfloat16* __restrict__ Bhi, const __nv_bfloat16* __restrict__ Blo,
    const float* __restrict__ bias, float* __restrict__ Cf,
    __half* __restrict__ Ch, int nrows) {
    constexpr int SA = 136;                   // padded row stride (bf16 elems)
    constexpr int BM = 64;
    constexpr int WCOL = NC / 32;             // warps along N
    constexpr int WROW = 8 / WCOL;            // warps along M
    constexpr int MT = BM / (WROW * 16);      // m16 atoms per warp
    extern __shared__ __nv_bfloat16 sm[];
    __nv_bfloat16* sAh = sm;                  // BM * SA
    __nv_bfloat16* sAl = sAh + BM * SA;
    __nv_bfloat16* sBh = sAl + BM * SA;       // NC * SA
    __nv_bfloat16* sBl = sBh + NC * SA;

    int tid = threadIdx.x;
    int wid = tid >> 5, lane = tid & 31;
    int wr = wid % WROW, wc = wid / WROW;
    int m0 = wr * MT * 16;
    int n0 = wc * 32;

    // ---- load B once ----
    for (int i = tid; i < NC * 16; i += 256) {
        int r = i >> 4, j = i & 15;
        *(uint4*)(sBh + r * SA + j * 8) = ((const uint4*)(Bhi + (size_t)r * 128))[j];
        *(uint4*)(sBl + r * SA + j * 8) = ((const uint4*)(Blo + (size_t)r * 128))[j];
    }

    uint32_t sbase = smem_u32(sm);
    uint32_t aAh = sbase;
    uint32_t aAl = aAh + BM * SA * 2;
    uint32_t aBh = aAl + BM * SA * 2;
    uint32_t aBl = aBh + NC * SA * 2;

    uint32_t arow = (uint32_t)(m0 + (lane & 15));
    uint32_t aksel = (uint32_t)((lane >> 4) * 8);
    uint32_t brow = (uint32_t)(n0 + (lane & 7));
    uint32_t bksel = (uint32_t)(((lane >> 3) & 1) * 8);

    const int tiles = (nrows + BM - 1) / BM;
    for (int tile = blockIdx.x; tile < tiles; tile += gridDim.x) {
        int row0 = tile * BM;

        __syncthreads();   // previous iteration's MMA reads of sA are done
        // load A tile: fp32 -> affine(+relu) -> split hi/lo -> smem
        for (int i = tid; i < BM * 32; i += 256) {
            int r = i >> 5, j = i & 31;
            int gr = row0 + r;
            float4 v = make_float4(0, 0, 0, 0);
            if (gr < nrows) v = ((const float4*)(Araw + (size_t)gr * 128))[j];
            float4 a = ((const float4*)trA)[j];
            float4 b = ((const float4*)trB)[j];
            float t0 = fmaf(v.x, a.x, b.x), t1 = fmaf(v.y, a.y, b.y);
            float t2 = fmaf(v.z, a.z, b.z), t3 = fmaf(v.w, a.w, b.w);
            if (relu) {
                t0 = fmaxf(t0, 0.f); t1 = fmaxf(t1, 0.f);
                t2 = fmaxf(t2, 0.f); t3 = fmaxf(t3, 0.f);
            }
            __nv_bfloat16 h0 = __float2bfloat16(t0), h1 = __float2bfloat16(t1);
            __nv_bfloat16 h2 = __float2bfloat16(t2), h3 = __float2bfloat16(t3);
            __nv_bfloat162 hh01(h0, h1), hh23(h2, h3);
            __nv_bfloat162 ll01(__float2bfloat16(t0 - __bfloat162float(h0)),
                                __float2bfloat16(t1 - __bfloat162float(h1)));
            __nv_bfloat162 ll23(__float2bfloat16(t2 - __bfloat162float(h2)),
                                __float2bfloat16(t3 - __bfloat162float(h3)));
            *(uint2*)(sAh + r * SA + j * 4) =
                make_uint2(*(uint32_t*)&hh01, *(uint32_t*)&hh23);
            *(uint2*)(sAl + r * SA + j * 4) =
                make_uint2(*(uint32_t*)&ll01, *(uint32_t*)&ll23);
        }
        __syncthreads();

        float acc[MT][4][4];
#pragma unroll
        for (int ma = 0; ma < MT; ma++)
#pragma unroll
            for (int na = 0; na < 4; na++)
#pragma unroll
                for (int j = 0; j < 4; j++) acc[ma][na][j] = 0.f;

#pragma unroll
        for (int ks = 0; ks < 8; ks++) {
            uint32_t koffA = (uint32_t)(ks * 16) + aksel;
            uint32_t koffB = (uint32_t)(ks * 16) + bksel;
            uint32_t Af[MT][4], Bf[4][2], Bf2[4][2];

            // term 1: Ah * Bh
#pragma unroll
            for (int ma = 0; ma < MT; ma++)
                ldsm_x4(Af[ma], aAh + ((arow + ma * 16) * SA + koffA) * 2);
#pragma unroll
            for (int na = 0; na < 4; na++)
                ldsm_x2(Bf[na], aBh + ((brow + na * 8) * SA + koffB) * 2);
#pragma unroll
            for (int ma = 0; ma < MT; ma++)
#pragma unroll
                for (int na = 0; na < 4; na++)
                    mma_bf16(acc[ma][na], Af[ma], Bf[na]);

            // term 2: Ah * Bl
#pragma unroll
            for (int na = 0; na < 4; na++)
                ldsm_x2(Bf2[na], aBl + ((brow + na * 8) * SA + koffB) * 2);
#pragma unroll
            for (int ma = 0; ma < MT; ma++)
#pragma unroll
                for (int na = 0; na < 4; na++)
                    mma_bf16(acc[ma][na], Af[ma], Bf2[na]);

            // term 3: Al * Bh
#pragma unroll
            for (int ma = 0; ma < MT; ma++)
                ldsm_x4(Af[ma], aAl + ((arow + ma * 16) * SA + koffA) * 2);
#pragma unroll
            for (int ma = 0; ma < MT; ma++)
#pragma unroll
                for (int na = 0; na < 4; na++)
                    mma_bf16(acc[ma][na], Af[ma], Bf[na]);
        }

        // epilogue
        int rbase = row0 + m0 + (lane >> 2);
        int cbase = n0 + (lane & 3) * 2;
#pragma unroll
        for (int ma = 0; ma < MT; ma++) {
#pragma unroll
            for (int half = 0; half < 2; half++) {
                int gr = rbase + ma * 16 + half * 8;
                if (gr >= nrows) continue;
#pragma unroll
                for (int na = 0; na < 4; na++) {
                    float v0 = acc[ma][na][half * 2 + 0];
                    float v1 = acc[ma][na][half * 2 + 1];
                    int c = cbase + na * 8;
                    if (MODE == 1) {
                        v0 = fmaxf(v0 + bias[c], 0.f);
                        v1 = fmaxf(v1 + bias[c + 1], 0.f);
                        *(float2*)(Cf + (size_t)gr * NC + c) = make_float2(v0, v1);
                    } else {
                        *(__half2*)(Ch + (size_t)gr * NC + c) =
                            __floats2half2_rn(v0, v1);
                    }
                }
            }
        }
    }
}

// ---------------- aggregation (fp16 messages) + residual + BN stats ---------
__global__ void k_agg(const __half* __restrict__ msg,
                      const float* __restrict__ trA, const float* __restrict__ trB,
                      int relu, const float* __restrict__ bias,
                      float* __restrict__ bnsum, float* __restrict__ bnsq) {
    int lane = threadIdx.x & 31;
    int w = (blockIdx.x * blockDim.x + threadIdx.x) >> 5;
    int nw = (gridDim.x * blockDim.x) >> 5;
    float4* h4 = (float4*)g_h;
    float4 b = ((const float4*)bias)[lane];
    float4 tA = ((const float4*)trA)[lane];
    float4 tB = ((const float4*)trB)[lane];

    float4 lsum = make_float4(0, 0, 0, 0);
    float4 lsq = make_float4(0, 0, 0, 0);

    for (int n = w; n < NN; n += nw) {
        float di = g_dinv[n];
        float sw = di * di;
        uint2 mu = ((const uint2*)(msg + (size_t)n * 128))[lane];
        float2 m01 = __half22float2(*(__half2*)&mu.x);
        float2 m23 = __half22float2(*(__half2*)&mu.y);
        float4 acc = make_float4(m01.x * sw, m01.y * sw, m23.x * sw, m23.y * sw);
        int p0 = g_rowstart[n], p1 = g_rowstart[n + 1];
        int p = p0;
        for (; p + 2 <= p1; p += 2) {
            int2 e0 = g_csr[p], e1 = g_csr[p + 1];
            uint2 u0 = ((const uint2*)(msg + (size_t)e0.x * 128))[lane];
            uint2 u1 = ((const uint2*)(msg + (size_t)e1.x * 128))[lane];
            float w0 = __int_as_float(e0.y), w1 = __int_as_float(e1.y);
            float2 a01 = __half22float2(*(__half2*)&u0.x);
            float2 a23 = __half22float2(*(__half2*)&u0.y);
            float2 c01 = __half22float2(*(__half2*)&u1.x);
            float2 c23 = __half22float2(*(__half2*)&u1.y);
            acc.x += a01.x * w0 + c01.x * w1;
            acc.y += a01.y * w0 + c01.y * w1;
            acc.z += a23.x * w0 + c23.x * w1;
            acc.w += a23.y * w0 + c23.y * w1;
        }
        if (p < p1) {
            int2 e0 = g_csr[p];
            uint2 u0 = ((const uint2*)(msg + (size_t)e0.x * 128))[lane];
            float w0 = __int_as_float(e0.y);
            float2 a01 = __half22float2(*(__half2*)&u0.x);
            float2 a23 = __half22float2(*(__half2*)&u0.y);
            acc.x += a01.x * w0; acc.y += a01.y * w0;
            acc.z += a23.x * w0; acc.w += a23.y * w0;
        }
        // apply previous layer's BN affine (+relu) to raw h, then residual add
        float4 hv = h4[(size_t)n * 32 + lane];
        float p0f = fmaf(hv.x, tA.x, tB.x), p1f = fmaf(hv.y, tA.y, tB.y);
        float p2f = fmaf(hv.z, tA.z, tB.z), p3f = fmaf(hv.w, tA.w, tB.w);
        if (relu) {
            p0f = fmaxf(p0f, 0.f); p1f = fmaxf(p1f, 0.f);
            p2f = fmaxf(p2f, 0.f); p3f = fmaxf(p3f, 0.f);
        }
        hv.x = p0f + acc.x + b.x; hv.y = p1f + acc.y + b.y;
        hv.z = p2f + acc.z + b.z; hv.w = p3f + acc.w + b.w;
        h4[(size_t)n * 32 + lane] = hv;
        lsum.x += hv.x; lsum.y += hv.y; lsum.z += hv.z; lsum.w += hv.w;
        lsq.x += hv.x * hv.x; lsq.y += hv.y * hv.y;
        lsq.z += hv.z * hv.z; lsq.w += hv.w * hv.w;
    }

    __shared__ float s_sum[HD], s_sq[HD];
    for (int i = threadIdx.x; i < HD; i += blockDim.x) { s_sum[i] = 0.f; s_sq[i] = 0.f; }
    __syncthreads();
    int c = lane * 4;
    atomicAdd(&s_sum[c + 0], lsum.x); atomicAdd(&s_sum[c + 1], lsum.y);
    atomicAdd(&s_sum[c + 2], lsum.z); atomicAdd(&s_sum[c + 3], lsum.w);
    atomicAdd(&s_sq[c + 0], lsq.x);  atomicAdd(&s_sq[c + 1], lsq.y);
    atomicAdd(&s_sq[c + 2], lsq.z);  atomicAdd(&s_sq[c + 3], lsq.w);
    __syncthreads();
    for (int i = threadIdx.x; i < HD; i += blockDim.x) {
        atomicAdd(&bnsum[i], s_sum[i]);
        atomicAdd(&bnsq[i], s_sq[i]);
    }
}

// ---------------- final 64 -> 8 projection ----------------------------------
__global__ void k_w3(const float* __restrict__ h2, const float* __restrict__ W3,
                     const float* __restrict__ b3, float* __restrict__ out) {
    int i = blockIdx.x * blockDim.x + threadIdx.x;
    if (i >= NN * 8) return;
    int n = i >> 3, o = i & 7;
    const float* hr = h2 + (size_t)n * 64;
    float s = b3[o];
#pragma unroll 8
    for (int k = 0; k < 64; k++) s += hr[k] * W3[k * 8 + o];
    out[i] = s;
}

// ---------------- host side -------------------------------------------------
extern "C" void kernel_launch(void* const* d_in, const int* in_sizes, int n_in,
                              void* d_out, int out_size) {
    const float* x    = (const float*)d_in[0];
    const int*   ei   = (const int*)d_in[1];
    const float* Wi   = (const float*)d_in[2];
    const float* bi   = (const float*)d_in[3];
    const float* gcnW = (const float*)d_in[4];
    const float* gcnb = (const float*)d_in[5];
    const float* bng  = (const float*)d_in[6];
    const float* bnb  = (const float*)d_in[7];
    const float* W1   = (const float*)d_in[8];
    const float* b1   = (const float*)d_in[9];
    const float* W2   = (const float*)d_in[10];
    const float* b2   = (const float*)d_in[11];
    const float* W3   = (const float*)d_in[12];
    const float* b3   = (const float*)d_in[13];
    float* out = (float*)d_out;

    float *p_h, *p_m, *p_bnsum, *p_bnsq, *p_trA, *p_trB;
    __nv_bfloat16 *p_wth, *p_wtl, *p_w2th, *p_w2tl;
    cudaGetSymbolAddress((void**)&p_h, g_h);
    cudaGetSymbolAddress((void**)&p_m, g_m);
    cudaGetSymbolAddress((void**)&p_bnsum, g_bnsum);
    cudaGetSymbolAddress((void**)&p_bnsq, g_bnsq);
    cudaGetSymbolAddress((void**)&p_trA, g_trA);
    cudaGetSymbolAddress((void**)&p_trB, g_trB);
    cudaGetSymbolAddress((void**)&p_wth, g_wth);
    cudaGetSymbolAddress((void**)&p_wtl, g_wtl);
    cudaGetSymbolAddress((void**)&p_w2th, g_w2th);
    cudaGetSymbolAddress((void**)&p_w2tl, g_w2tl);
    __half* p_msg = (__half*)p_m;   // fp16 messages alias the fp32 temp buffer

    constexpr int SA = 136;
    constexpr int SM128 = (64 * 2 + 128 * 2) * SA * 2;  // 104448 B -> 2 CTA/SM
    constexpr int SM64  = (64 * 2 + 64 * 2) * SA * 2;   // 69632 B
    cudaFuncSetAttribute((const void*)k_tgemm<128, 0>,
                         cudaFuncAttributeMaxDynamicSharedMemorySize, SM128);
    cudaFuncSetAttribute((const void*)k_tgemm<128, 1>,
                         cudaFuncAttributeMaxDynamicSharedMemorySize, SM128);
    cudaFuncSetAttribute((const void*)k_tgemm<64, 1>,
                         cudaFuncAttributeMaxDynamicSharedMemorySize, SM64);

    k_zero<<<(NN + 255) / 256, 256>>>();
    k_count<<<(NE + 255) / 256, 256>>>(ei);
    k_scan<<<1, 1024>>>();
    k_fill<<<(NE + 255) / 256, 256>>>(ei);
    k_wprep<<<(5 * HD * HD + 64 * HD + 255) / 256, 256>>>(gcnW, W1, W2);
    k_proj<<<(NN * HD + 255) / 256, 256>>>(x, Wi, bi);

    for (int l = 0; l < LAYERS; l++) {
        k_tgemm<128, 0><<<GEMM_GRID, 256, SM128>>>(
            p_h, p_trA + l * HD, p_trB + l * HD, l > 0,
            p_wth + l * HD * HD, p_wtl + l * HD * HD, nullptr, nullptr, p_msg, NN);
        k_agg<<<1184, 256>>>(p_msg, p_trA + l * HD, p_trB + l * HD, l > 0,
                             gcnb + l * HD, p_bnsum + l * HD, p_bnsq + l * HD);
        k_bnprep<<<1, 128>>>(bng + l * HD, bnb + l * HD, p_bnsum + l * HD,
                             p_bnsq + l * HD, p_trA + (l + 1) * HD,
                             p_trB + (l + 1) * HD);
    }

    k_tgemm<128, 1><<<GEMM_GRID, 256, SM128>>>(
        p_h, p_trA + LAYERS * HD, p_trB + LAYERS * HD, 1,
        p_wth + 4 * HD * HD, p_wtl + 4 * HD * HD, b1, p_m, nullptr, NN);
    k_tgemm<64, 1><<<GEMM_GRID, 256, SM64>>>(
        p_m, p_trA, p_trB, 0, p_w2th, p_w2tl, b2, p_h, nullptr, NN);
    k_w3<<<(NN * 8 + 255) / 256, 256>>>(p_h, W3, b3, out);
}